// round 14
// baseline (speedup 1.0000x reference)
#include <cuda_runtime.h>

#define NODES 7
#define CH 256
#define PAIRS 128
#define HID 128
#define P_TOTAL 65536
#define PF 8                    // prefetch depth (channel pairs)

typedef unsigned long long ull;

__device__ float g_nw[2 * NODES * CH];          // new_weight [b, n, c]
__device__ float g_attn[2 * NODES * P_TOTAL];   // attn scratch [b, n, p] (3.7MB)

// ---------------------------------------------------------------------------
__device__ __forceinline__ ull fma2(ull a, ull b, ull c) {
    ull d;
    asm("fma.rn.f32x2 %0, %1, %2, %3;" : "=l"(d) : "l"(a), "l"(b), "l"(c));
    return d;
}
__device__ __forceinline__ ull pack2(float x, float y) {
    ull r;
    asm("mov.b64 %0, {%1, %2};" : "=l"(r) : "f"(x), "f"(y));
    return r;
}
__device__ __forceinline__ void unpack2(ull v, float& x, float& y) {
    asm("mov.b64 {%0, %1}, %2;" : "=f"(x), "=f"(y) : "l"(v));
}
__device__ __forceinline__ float ldcs32(const float* p) {
    float v;
    asm volatile("ld.global.cs.b32 %0, [%1];" : "=f"(v) : "l"(p));
    return v;
}
__device__ __forceinline__ ull ldg64(const float* p) {
    ull v;
    asm volatile("ld.global.b64 %0, [%1];" : "=l"(v) : "l"(p));
    return v;
}
__device__ __forceinline__ void stcs64(float* p, ull v) {
    asm volatile("st.global.cs.b64 [%0], %1;" :: "l"(p), "l"(v));
}
__device__ __forceinline__ void st32(float* p, float v) {
    asm volatile("st.global.b32 [%0], %1;" :: "l"(p), "f"(v));
}

// ---------------------------------------------------------------------------
// pass1 body: one batch tile of 256 points (256 threads, 1 point/thread).
// Streams 64KB x 256 channels of res; n1 -> softmax -> g_attn (plain stores,
// stays L2-resident for the following pass2).
// ---------------------------------------------------------------------------
__device__ __forceinline__ void pass1_body(
    int b, int tile,
    const float* __restrict__ inp,
    const float* __restrict__ res,
    const float* __restrict__ Wres,
    const float* __restrict__ nfh)
{
    __shared__ ull W2[PAIRS][8];
    __shared__ float sh_n2[8];

    const int tid  = threadIdx.x;
    const int wid  = tid >> 5;
    const int lane = tid & 31;

    if (wid < NODES) {
        float s = 0.f;
#pragma unroll
        for (int i = 0; i < 4; ++i) {
            int h = lane + 32 * i;
            s += __ldg(inp + b * NODES * HID + wid * HID + h) * __ldg(nfh + h);
        }
#pragma unroll
        for (int o = 16; o; o >>= 1)
            s += __shfl_xor_sync(0xffffffffu, s, o);
        if (lane == 0) sh_n2[wid] = s;
    }
    if (tid < PAIRS) {
        const int k = tid;
#pragma unroll
        for (int n = 0; n < NODES; ++n) {
            float w0 = Wres[(2 * k) * NODES + n];
            float w1 = Wres[(2 * k + 1) * NODES + n];
            W2[k][n] = pack2(w0, w1);
        }
        W2[k][7] = 0ull;
    }
    __syncthreads();

    float n2s[NODES];
#pragma unroll
    for (int n = 0; n < NODES; ++n) n2s[n] = sh_n2[n];

    const int p = tile * 256 + tid;
    const float* rfp = res + (size_t)b * CH * P_TOTAL + p;

    ull acc[NODES];
#pragma unroll
    for (int n = 0; n < NODES; ++n) acc[n] = 0ull;

    float a0[PF], a1[PF];
#pragma unroll
    for (int i = 0; i < PF; ++i) {
        a0[i] = ldcs32(rfp + (size_t)(2 * i) * P_TOTAL);
        a1[i] = ldcs32(rfp + (size_t)(2 * i + 1) * P_TOTAL);
    }

#pragma unroll 1
    for (int kb = 0; kb < PAIRS; kb += PF) {
#pragma unroll
        for (int i = 0; i < PF; ++i) {
            ull v = pack2(a0[i], a1[i]);
            if (kb + PF < PAIRS) {
                a0[i] = ldcs32(rfp + (size_t)(2 * (kb + PF + i)) * P_TOTAL);
                a1[i] = ldcs32(rfp + (size_t)(2 * (kb + PF + i) + 1) * P_TOTAL);
            }
            const ulonglong2* wr = (const ulonglong2*)(&W2[kb + i][0]);
            ulonglong2 w01 = wr[0];
            ulonglong2 w23 = wr[1];
            ulonglong2 w45 = wr[2];
            ulonglong2 w6p = wr[3];
            acc[0] = fma2(v, w01.x, acc[0]);
            acc[1] = fma2(v, w01.y, acc[1]);
            acc[2] = fma2(v, w23.x, acc[2]);
            acc[3] = fma2(v, w23.y, acc[3]);
            acc[4] = fma2(v, w45.x, acc[4]);
            acc[5] = fma2(v, w45.y, acc[5]);
            acc[6] = fma2(v, w6p.x, acc[6]);
        }
    }

    float s[NODES];
#pragma unroll
    for (int n = 0; n < NODES; ++n) {
        float lo, hi;
        unpack2(acc[n], lo, hi);
        s[n] = lo + hi + n2s[n];
    }
    float m = s[0];
#pragma unroll
    for (int n = 1; n < NODES; ++n) m = fmaxf(m, s[n]);
    float e[NODES], sum = 0.f;
#pragma unroll
    for (int n = 0; n < NODES; ++n) { e[n] = __expf(s[n] - m); sum += e[n]; }
    float inv = __fdividef(1.f, sum);
#pragma unroll
    for (int n = 0; n < NODES; ++n)
        st32(&g_attn[(b * NODES + n) * P_TOTAL + p], e[n] * inv);
}

// ---------------------------------------------------------------------------
// pass2 body: one batch tile of 512 points (256 threads, 2 points/thread).
// ---------------------------------------------------------------------------
__device__ __forceinline__ void pass2_body(
    int b, int tile, float* __restrict__ out)
{
    __shared__ ull NW[CH][8];

    const int tid = threadIdx.x;
    {
        const int c = tid;
#pragma unroll
        for (int n = 0; n < NODES; ++n) {
            float q = g_nw[(b * NODES + n) * CH + c];
            NW[c][n] = pack2(q, q);
        }
        NW[c][7] = 0ull;
    }
    __syncthreads();

    const int p0 = tile * 512 + 2 * tid;

    ull at[NODES];
#pragma unroll
    for (int n = 0; n < NODES; ++n)
        at[n] = ldg64(&g_attn[(b * NODES + n) * P_TOTAL + p0]);

    float* op = out + (size_t)b * CH * P_TOTAL + p0;
#pragma unroll 4
    for (int c = 0; c < CH; ++c) {
        const ulonglong2* nr = (const ulonglong2*)(&NW[c][0]);
        ulonglong2 q01 = nr[0];
        ulonglong2 q23 = nr[1];
        ulonglong2 q45 = nr[2];
        ulonglong2 q6p = nr[3];
        ull o = 0ull;
        o = fma2(at[0], q01.x, o);
        o = fma2(at[1], q01.y, o);
        o = fma2(at[2], q23.x, o);
        o = fma2(at[3], q23.y, o);
        o = fma2(at[4], q45.x, o);
        o = fma2(at[5], q45.y, o);
        o = fma2(at[6], q6p.x, o);
        float v0, v1;
        unpack2(o, v0, v1);
        stcs64(op + (size_t)c * P_TOTAL, pack2(fmaxf(v0, 0.f), fmaxf(v1, 0.f)));
    }
}

// ---------------------------------------------------------------------------
// K_A: pure read phase — pass1(b=0) [256 blocks] + new_weight GEMM [14 blocks]
// ---------------------------------------------------------------------------
__global__ void __launch_bounds__(256, 4) kernel_A(
    const float* __restrict__ inp,
    const float* __restrict__ res,
    const float* __restrict__ Wres,
    const float* __restrict__ nfh,
    const float* __restrict__ weight)
{
    const int bid = blockIdx.x;
    if (bid >= 256) {
        const int bn = bid - 256;        // 0..13 = b*7+n
        const int tid = threadIdx.x;
        float acc = 0.f;
#pragma unroll 16
        for (int h = 0; h < HID; ++h)
            acc += __ldg(inp + bn * HID + h) * weight[h * CH + tid];
        g_nw[bn * CH + tid] = acc;
        return;
    }
    pass1_body(0, bid, inp, res, Wres, nfh);
}

// ---------------------------------------------------------------------------
// K_B: mixed phase — pass1(b=1) [blocks 0..255] + pass2(b=0) [blocks 256..383]
// ---------------------------------------------------------------------------
__global__ void __launch_bounds__(256, 4) kernel_B(
    const float* __restrict__ inp,
    const float* __restrict__ res,
    const float* __restrict__ Wres,
    const float* __restrict__ nfh,
    float* __restrict__ out)
{
    const int bid = blockIdx.x;
    if (bid < 256)
        pass1_body(1, bid, inp, res, Wres, nfh);
    else
        pass2_body(0, bid - 256, out);
}

// ---------------------------------------------------------------------------
// K_C: pure write phase — pass2(b=1) [128 blocks]
// ---------------------------------------------------------------------------
__global__ void __launch_bounds__(256, 4) kernel_C(float* __restrict__ out)
{
    pass2_body(1, blockIdx.x, out);
}

// ---------------------------------------------------------------------------
extern "C" void kernel_launch(void* const* d_in, const int* in_sizes, int n_in,
                              void* d_out, int out_size) {
    const float* inp    = (const float*)d_in[0];  // [1,2,7,128]
    const float* res    = (const float*)d_in[1];  // [2,256,16,64,64]
    const float* Wres   = (const float*)d_in[2];  // [256,7]
    const float* nfh    = (const float*)d_in[3];  // [128,1]
    const float* weight = (const float*)d_in[4];  // [128,256]
    float* out = (float*)d_out;

    kernel_A<<<270, 256>>>(inp, res, Wres, nfh, weight);
    kernel_B<<<384, 256>>>(inp, res, Wres, nfh, out);
    kernel_C<<<128, 256>>>(out);
}

// round 15
// speedup vs baseline: 1.0447x; 1.0447x over previous
#include <cuda_runtime.h>

#define NODES 7
#define CH 256
#define PAIRS 128
#define HID 128
#define P_TOTAL 65536
#define PF 8                    // prefetch depth (channel pairs per half)
#define GEMM_BLKS 14
#define P1_STREAM 1024          // pass1 stream blocks
#define WCH 64                  // channels written by pass1 (0..63)
#define WPAIRS 32               // channel pairs written by pass1

typedef unsigned long long ull;

__device__ float g_nw[2 * NODES * CH];          // new_weight [b, n, c]
__device__ float g_attn[2 * NODES * P_TOTAL];   // attn scratch [b, n, p]
__device__ int   g_done = 0;                    // GEMM blocks completed
__device__ int   g_fin  = 0;                    // stream blocks completed

// ---------------------------------------------------------------------------
__device__ __forceinline__ ull fma2(ull a, ull b, ull c) {
    ull d;
    asm("fma.rn.f32x2 %0, %1, %2, %3;" : "=l"(d) : "l"(a), "l"(b), "l"(c));
    return d;
}
__device__ __forceinline__ ull pack2(float x, float y) {
    ull r;
    asm("mov.b64 %0, {%1, %2};" : "=l"(r) : "f"(x), "f"(y));
    return r;
}
__device__ __forceinline__ void unpack2(ull v, float& x, float& y) {
    asm("mov.b64 {%0, %1}, %2;" : "=f"(x), "=f"(y) : "l"(v));
}
__device__ __forceinline__ float ldcs32(const float* p) {
    float v;
    asm volatile("ld.global.cs.b32 %0, [%1];" : "=f"(v) : "l"(p));
    return v;
}
__device__ __forceinline__ ull ldg64(const float* p) {
    ull v;
    asm volatile("ld.global.b64 %0, [%1];" : "=l"(v) : "l"(p));
    return v;
}
__device__ __forceinline__ void stcs32(float* p, float v) {
    asm volatile("st.global.cs.b32 [%0], %1;" :: "l"(p), "f"(v));
}
__device__ __forceinline__ void stcs64(float* p, ull v) {
    asm volatile("st.global.cs.b64 [%0], %1;" :: "l"(p), "l"(v));
}
__device__ __forceinline__ void st32(float* p, float v) {
    asm volatile("st.global.b32 [%0], %1;" :: "l"(p), "f"(v));
}

// ---------------------------------------------------------------------------
// Pass 1 (mixed stream): res (128MB read) -> n1 -> softmax -> g_attn (L2)
//                        + out channels [0,64) (32MB write).
//   Blocks 0..13    : new_weight GEMM -> g_nw, signal g_done. (first wave)
//   Blocks 14..1037 : stream; 2-way channel split, 1 point/thread.
// ---------------------------------------------------------------------------
__global__ void __launch_bounds__(256, 4) pass1_kernel(
    const float* __restrict__ inp,     // [1,2,7,128]
    const float* __restrict__ res,     // [2, 256, 65536]
    const float* __restrict__ Wres,    // [256, 7]
    const float* __restrict__ nfh,     // [128,1]
    const float* __restrict__ weight,  // [128, 256]
    float* __restrict__ out)           // [2, 256, 65536]
{
    const int tid = threadIdx.x;
    const int bid = blockIdx.x;

    // ---- GEMM blocks (bid 0..13, guaranteed wave 1) ----
    if (bid < GEMM_BLKS) {
        const int bn = bid;              // 0..13 = b*7+n
        float acc = 0.f;
#pragma unroll 16
        for (int h = 0; h < HID; ++h)
            acc += __ldg(inp + bn * HID + h) * weight[h * CH + tid];
        g_nw[bn * CH + tid] = acc;
        __syncthreads();
        __threadfence();
        if (tid == 0) atomicAdd(&g_done, 1);
        return;
    }

    __shared__ ull W2[PAIRS][8];          // (w[2k][n], w[2k+1][n])
    __shared__ ull NW2[WPAIRS][8];        // packed nw for write channels
    __shared__ float part[NODES][2][128]; // cross-half partials
    __shared__ float sh_n2[8];

    const int tg   = bid - GEMM_BLKS;    // 0..1023
    const int half = tid >> 7;           // channel half
    const int pl   = tid & 127;
    const int b    = tg >> 9;            // 0..1
    const int tile = tg & 511;
    const int p    = tile * 128 + pl;
    const int wid  = tid >> 5;
    const int lane = tid & 31;

    // n2[b][n]: warp n computes the 128-dot via shuffle
    if (wid < NODES) {
        float s = 0.f;
#pragma unroll
        for (int i = 0; i < 4; ++i) {
            int h = lane + 32 * i;
            s += __ldg(inp + b * NODES * HID + wid * HID + h) * __ldg(nfh + h);
        }
#pragma unroll
        for (int o = 16; o; o >>= 1)
            s += __shfl_xor_sync(0xffffffffu, s, o);
        if (lane == 0) sh_n2[wid] = s;
    }
    if (tid < PAIRS) {
        const int k = tid;
#pragma unroll
        for (int n = 0; n < NODES; ++n) {
            float w0 = Wres[(2 * k) * NODES + n];
            float w1 = Wres[(2 * k + 1) * NODES + n];
            W2[k][n] = pack2(w0, w1);
        }
        W2[k][7] = 0ull;
    }
    __syncthreads();

    float n2s[NODES];
#pragma unroll
    for (int n = 0; n < NODES; ++n) n2s[n] = sh_n2[n];

    const int kbase = half * 64;
    const float* rfp = res + (size_t)b * CH * P_TOTAL
                           + (size_t)(half * 128) * P_TOTAL + p;

    ull acc[NODES];
#pragma unroll
    for (int n = 0; n < NODES; ++n) acc[n] = 0ull;

    // ---- read stream: this half's 128 channels
    float a0[PF], a1[PF];
#pragma unroll
    for (int i = 0; i < PF; ++i) {
        a0[i] = ldcs32(rfp + (size_t)(2 * i) * P_TOTAL);
        a1[i] = ldcs32(rfp + (size_t)(2 * i + 1) * P_TOTAL);
    }

#pragma unroll 1
    for (int jb = 0; jb < 64; jb += PF) {
#pragma unroll
        for (int i = 0; i < PF; ++i) {
            ull v = pack2(a0[i], a1[i]);
            if (jb + PF < 64) {
                a0[i] = ldcs32(rfp + (size_t)(2 * (jb + PF + i)) * P_TOTAL);
                a1[i] = ldcs32(rfp + (size_t)(2 * (jb + PF + i) + 1) * P_TOTAL);
            }
            const ulonglong2* wr = (const ulonglong2*)(&W2[kbase + jb + i][0]);
            ulonglong2 w01 = wr[0];
            ulonglong2 w23 = wr[1];
            ulonglong2 w45 = wr[2];
            ulonglong2 w6p = wr[3];
            acc[0] = fma2(v, w01.x, acc[0]);
            acc[1] = fma2(v, w01.y, acc[1]);
            acc[2] = fma2(v, w23.x, acc[2]);
            acc[3] = fma2(v, w23.y, acc[3]);
            acc[4] = fma2(v, w45.x, acc[4]);
            acc[5] = fma2(v, w45.y, acc[5]);
            acc[6] = fma2(v, w6p.x, acc[6]);
        }
    }

    // ---- exchange partials between halves
    float myp[NODES];
#pragma unroll
    for (int n = 0; n < NODES; ++n) {
        float lo, hi;
        unpack2(acc[n], lo, hi);
        myp[n] = lo + hi;
        part[n][half][pl] = myp[n];
    }
    __syncthreads();

    float s[NODES];
#pragma unroll
    for (int n = 0; n < NODES; ++n)
        s[n] = myp[n] + part[n][half ^ 1][pl] + n2s[n];

    // ---- softmax
    float m = s[0];
#pragma unroll
    for (int n = 1; n < NODES; ++n) m = fmaxf(m, s[n]);
    float e[NODES], sum = 0.f;
#pragma unroll
    for (int n = 0; n < NODES; ++n) { e[n] = __expf(s[n] - m); sum += e[n]; }
    float inv = __fdividef(1.f, sum);

    // attn to scratch (split: half0 -> nodes 0..3, half1 -> 4..6), plain st
    if (half == 0) {
#pragma unroll
        for (int n = 0; n < 4; ++n)
            st32(&g_attn[(b * NODES + n) * P_TOTAL + p], e[n] * inv);
    } else {
#pragma unroll
        for (int n = 4; n < NODES; ++n)
            st32(&g_attn[(b * NODES + n) * P_TOTAL + p], e[n] * inv);
    }

    ull attn2[NODES];
#pragma unroll
    for (int n = 0; n < NODES; ++n) {
        float a = e[n] * inv;
        attn2[n] = pack2(a, a);
    }

    // ---- wait for GEMM (expected zero spin), stage NW2 for write channels
    if (tid == 0) {
        while (*(volatile int*)&g_done < GEMM_BLKS) { }
    }
    __syncthreads();
    __threadfence();
    if (tid < WPAIRS) {
        const int k = tid;
#pragma unroll
        for (int n = 0; n < NODES; ++n) {
            float q0 = g_nw[(b * NODES + n) * CH + 2 * k];
            float q1 = g_nw[(b * NODES + n) * CH + 2 * k + 1];
            NW2[k][n] = pack2(q0, q1);
        }
        NW2[k][7] = 0ull;
    }
    __syncthreads();

    // ---- mixed-phase write: out channels [32*half, 32*half+32) for point p
    float* op = out + (size_t)b * CH * P_TOTAL + p;
    const int wkbase = half * 16;        // pair range per half
#pragma unroll 4
    for (int j = 0; j < 16; ++j) {
        const int k = wkbase + j;
        const ulonglong2* nr = (const ulonglong2*)(&NW2[k][0]);
        ulonglong2 q01 = nr[0];
        ulonglong2 q23 = nr[1];
        ulonglong2 q45 = nr[2];
        ulonglong2 q6p = nr[3];
        ull o = 0ull;
        o = fma2(attn2[0], q01.x, o);
        o = fma2(attn2[1], q01.y, o);
        o = fma2(attn2[2], q23.x, o);
        o = fma2(attn2[3], q23.y, o);
        o = fma2(attn2[4], q45.x, o);
        o = fma2(attn2[5], q45.y, o);
        o = fma2(attn2[6], q6p.x, o);
        float v0, v1;
        unpack2(o, v0, v1);
        stcs32(op + (size_t)(2 * k) * P_TOTAL,     fmaxf(v0, 0.f));
        stcs32(op + (size_t)(2 * k + 1) * P_TOTAL, fmaxf(v1, 0.f));
    }

    // ---- completion accounting; last stream block resets counters
    __syncthreads();
    if (tid == 0) {
        __threadfence();
        int v = atomicAdd(&g_fin, 1);
        if (v == P1_STREAM - 1) {
            atomicExch(&g_done, 0);
            atomicExch(&g_fin, 0);
        }
    }
}

// ---------------------------------------------------------------------------
// Pass 2: PURE WRITE stream for channels [64, 256). g_attn (L2) + g_nw -> out.
// 2 points/thread, 256 blocks x 256 threads. 96 MB.
// ---------------------------------------------------------------------------
__global__ void __launch_bounds__(256, 6) pass2_kernel(
    float* __restrict__ out)           // [2, 256, 65536]
{
    __shared__ ull NW[CH - WCH][8];    // duplicated nw, channels 64..255

    const int tid  = threadIdx.x;
    const int b    = blockIdx.x >> 7;
    const int tile = blockIdx.x & 127;

    if (tid < CH - WCH) {
        const int c = WCH + tid;
#pragma unroll
        for (int n = 0; n < NODES; ++n) {
            float q = g_nw[(b * NODES + n) * CH + c];
            NW[tid][n] = pack2(q, q);
        }
        NW[tid][7] = 0ull;
    }
    __syncthreads();

    const int p0 = tile * 512 + 2 * tid;

    ull at[NODES];
#pragma unroll
    for (int n = 0; n < NODES; ++n)
        at[n] = ldg64(&g_attn[(b * NODES + n) * P_TOTAL + p0]);

    float* op = out + (size_t)b * CH * P_TOTAL + (size_t)WCH * P_TOTAL + p0;
#pragma unroll 4
    for (int c = 0; c < CH - WCH; ++c) {
        const ulonglong2* nr = (const ulonglong2*)(&NW[c][0]);
        ulonglong2 q01 = nr[0];
        ulonglong2 q23 = nr[1];
        ulonglong2 q45 = nr[2];
        ulonglong2 q6p = nr[3];
        ull o = 0ull;
        o = fma2(at[0], q01.x, o);
        o = fma2(at[1], q01.y, o);
        o = fma2(at[2], q23.x, o);
        o = fma2(at[3], q23.y, o);
        o = fma2(at[4], q45.x, o);
        o = fma2(at[5], q45.y, o);
        o = fma2(at[6], q6p.x, o);
        float v0, v1;
        unpack2(o, v0, v1);
        stcs64(op + (size_t)c * P_TOTAL, pack2(fmaxf(v0, 0.f), fmaxf(v1, 0.f)));
    }
}

// ---------------------------------------------------------------------------
extern "C" void kernel_launch(void* const* d_in, const int* in_sizes, int n_in,
                              void* d_out, int out_size) {
    const float* inp    = (const float*)d_in[0];  // [1,2,7,128]
    const float* res    = (const float*)d_in[1];  // [2,256,16,64,64]
    const float* Wres   = (const float*)d_in[2];  // [256,7]
    const float* nfh    = (const float*)d_in[3];  // [128,1]
    const float* weight = (const float*)d_in[4];  // [128,256]

    pass1_kernel<<<GEMM_BLKS + P1_STREAM, 256>>>(inp, res, Wres, nfh, weight,
                                                 (float*)d_out);
    pass2_kernel<<<256, 256>>>((float*)d_out);
}